// round 9
// baseline (speedup 1.0000x reference)
#include <cuda_runtime.h>
#include <mma.h>
#include <math.h>
#include <stdint.h>

using namespace nvcuda;

#define NN 50000
#define NE 800000
#define F  128
#define MT 128       // rows per MMA block
#define ALD 136      // smem leading dim (mult of 8)

// ---------------- scratch (device globals; no allocation allowed) ----------
__device__ __align__(16) float g_feat[NN * F];
__device__ __align__(16) float g_h1[NN * F];
__device__ __align__(16) float g_h2[NN * F];
__device__ __align__(16) float g_el[NN * 4];
__device__ __align__(16) float g_er[NN * 4];
__device__ __align__(16) float g_wl[4 * F];   // W @ al[h]
__device__ __align__(16) float g_wr[4 * F];   // W @ ar[h]
__device__ int g_rowptr[NN + 1];
__device__ unsigned g_elmax_u[3][4];

// ---------------- monotone float<->uint encode for atomicMax ---------------
__device__ __forceinline__ unsigned fenc(float f) {
    unsigned u = __float_as_uint(f);
    return (u & 0x80000000u) ? ~u : (u | 0x80000000u);
}
__device__ __forceinline__ float fdec(unsigned u) {
    return (u & 0x80000000u) ? __uint_as_float(u ^ 0x80000000u)
                             : __uint_as_float(~u);
}

// ---------------- row_ptr (sorted dst, lower_bound) + elmax reset ----------
__global__ void rowptr_kernel(const int* __restrict__ dst) {
    int n = blockIdx.x * blockDim.x + threadIdx.x;
    if (blockIdx.x == 0 && threadIdx.x < 12)
        ((unsigned*)g_elmax_u)[threadIdx.x] = fenc(-3.0e38f);
    if (n > NN) return;
    int lo = 0, hi = NE;
    while (lo < hi) {
        int mid = (lo + hi) >> 1;
        if (dst[mid] < n) lo = mid + 1; else hi = mid;
    }
    g_rowptr[n] = lo;
}

// ---------------- per-layer W prep: wl[h]=W@al[h], wr[h]=W@ar[h] -----------
__global__ __launch_bounds__(256) void wprep_kernel(
    const float* __restrict__ W, const float* __restrict__ al,
    const float* __restrict__ ar)
{
    const int tid = threadIdx.x;
    #pragma unroll
    for (int j = 0; j < 4; j++) {
        int o = tid + 256 * j;                 // 1024 outputs
        int k = o & 127, hh = o >> 7, h = hh & 3;
        const float* vec = (hh < 4) ? al : ar;
        float s = 0.f;
        #pragma unroll
        for (int d = 0; d < 32; d++)
            s = fmaf(__ldg(&W[k * F + h * 32 + d]), __ldg(&vec[h * 32 + d]), s);
        if (hh < 4) g_wl[h * F + k] = s; else g_wr[h * F + k] = s;
    }
}

// ---------------- exact fp32 scores: el/er = h @ wl/wr + elmax -------------
__global__ __launch_bounds__(256) void scores_kernel(
    const float* __restrict__ hin, int slot)
{
    __shared__ unsigned shm[4];
    const int tid = threadIdx.x;
    if (tid < 4) shm[tid] = fenc(-3.0e38f);
    __syncthreads();

    const int gw = (blockIdx.x * 256 + tid) >> 5;
    const int lane = tid & 31;
    if (gw < NN) {
        float4 f = __ldg(reinterpret_cast<const float4*>(&hin[gw * F + 4 * lane]));
        const float4* wl4 = reinterpret_cast<const float4*>(g_wl);
        const float4* wr4 = reinterpret_cast<const float4*>(g_wr);
        float pel[4], per_[4];
        #pragma unroll
        for (int h = 0; h < 4; h++) {
            float4 a = __ldg(&wl4[h * 32 + lane]);
            pel[h] = fmaf(f.x, a.x, fmaf(f.y, a.y, fmaf(f.z, a.z, f.w * a.w)));
            float4 b = __ldg(&wr4[h * 32 + lane]);
            per_[h] = fmaf(f.x, b.x, fmaf(f.y, b.y, fmaf(f.z, b.z, f.w * b.w)));
        }
        #pragma unroll
        for (int off = 16; off > 0; off >>= 1) {
            #pragma unroll
            for (int h = 0; h < 4; h++) {
                pel[h] += __shfl_xor_sync(0xffffffffu, pel[h], off);
                per_[h] += __shfl_xor_sync(0xffffffffu, per_[h], off);
            }
        }
        if (lane == 0) {
            *reinterpret_cast<float4*>(&g_el[gw * 4]) =
                make_float4(pel[0], pel[1], pel[2], pel[3]);
            *reinterpret_cast<float4*>(&g_er[gw * 4]) =
                make_float4(per_[0], per_[1], per_[2], per_[3]);
            atomicMax(&shm[0], fenc(pel[0]));
            atomicMax(&shm[1], fenc(pel[1]));
            atomicMax(&shm[2], fenc(pel[2]));
            atomicMax(&shm[3], fenc(pel[3]));
        }
    }
    __syncthreads();
    if (tid < 4) atomicMax(&g_elmax_u[slot][tid], shm[tid]);
}

// ---------------- WMMA TF32 GEMM: feat = h @ W (fp32 out) ------------------
// 128x128 tile per CTA, 256 threads / 8 warps (2x4 warp grid, warp = 32x64).
// A (h tile) and B (W) staged in shared, tf32-rounded at fill time.
extern __shared__ float s_mma[];

__global__ __launch_bounds__(256, 1) void mma_kernel(
    const float* __restrict__ hin, const float* __restrict__ W)
{
    float* As = s_mma;               // [128][ALD]
    float* Bs = s_mma + MT * ALD;    // [128][ALD]
    const int tid  = threadIdx.x;
    const int base = blockIdx.x * MT;

    // ---- fill A (h rows, zero-pad OOB) and B (W), tf32-rounded ----
    #pragma unroll
    for (int i = 0; i < 16; i++) {
        int idx = tid + 256 * i;          // 4096 float4 slots
        int row = idx >> 5, c4 = idx & 31;
        int n = base + row;
        float4 v = (n < NN)
            ? __ldg(reinterpret_cast<const float4*>(&hin[n * F + 4 * c4]))
            : make_float4(0.f, 0.f, 0.f, 0.f);
        v.x = wmma::__float_to_tf32(v.x);
        v.y = wmma::__float_to_tf32(v.y);
        v.z = wmma::__float_to_tf32(v.z);
        v.w = wmma::__float_to_tf32(v.w);
        *reinterpret_cast<float4*>(&As[row * ALD + 4 * c4]) = v;

        float4 wv = __ldg(reinterpret_cast<const float4*>(&W[idx * 4]));
        wv.x = wmma::__float_to_tf32(wv.x);
        wv.y = wmma::__float_to_tf32(wv.y);
        wv.z = wmma::__float_to_tf32(wv.z);
        wv.w = wmma::__float_to_tf32(wv.w);
        int wk = idx >> 5, wc = idx & 31;
        *reinterpret_cast<float4*>(&Bs[wk * ALD + 4 * wc]) = wv;
    }
    __syncthreads();

    const int w  = tid >> 5;
    const int wr = w & 3;       // row block: rows 32*wr .. +31
    const int wc = w >> 2;      // col block: cols 64*wc .. +63

    wmma::fragment<wmma::accumulator, 16, 16, 8, float> c[2][4];
    #pragma unroll
    for (int i = 0; i < 2; i++)
        #pragma unroll
        for (int j = 0; j < 4; j++) wmma::fill_fragment(c[i][j], 0.f);

    #pragma unroll
    for (int k = 0; k < 16; k++) {
        wmma::fragment<wmma::matrix_a, 16, 16, 8, wmma::precision::tf32,
                       wmma::row_major> a[2];
        wmma::fragment<wmma::matrix_b, 16, 16, 8, wmma::precision::tf32,
                       wmma::row_major> b[4];
        #pragma unroll
        for (int i = 0; i < 2; i++)
            wmma::load_matrix_sync(a[i], &As[(32 * wr + 16 * i) * ALD + 8 * k], ALD);
        #pragma unroll
        for (int j = 0; j < 4; j++)
            wmma::load_matrix_sync(b[j], &Bs[8 * k * ALD + 64 * wc + 16 * j], ALD);
        #pragma unroll
        for (int i = 0; i < 2; i++)
            #pragma unroll
            for (int j = 0; j < 4; j++)
                wmma::mma_sync(c[i][j], a[i], b[j], c[i][j]);
    }
    __syncthreads();   // all warps done reading As before reuse as C staging

    #pragma unroll
    for (int i = 0; i < 2; i++)
        #pragma unroll
        for (int j = 0; j < 4; j++)
            wmma::store_matrix_sync(
                &As[(32 * wr + 16 * i) * ALD + 64 * wc + 16 * j],
                c[i][j], ALD, wmma::mem_row_major);
    __syncthreads();

    // ---- bounded copy to g_feat (fp32) ----
    #pragma unroll
    for (int i = 0; i < 16; i++) {
        int idx = tid + 256 * i;
        int row = idx >> 5, c4 = idx & 31;
        int n = base + row;
        if (n < NN)
            *reinterpret_cast<float4*>(&g_feat[n * F + 4 * c4]) =
                *reinterpret_cast<const float4*>(&As[row * ALD + 4 * c4]);
    }
}

// ---------------- single-pass edge softmax + aggregation -------------------
// One warp per dst node; m = leaky(global_max(el)+er[n]) valid shift.
__global__ __launch_bounds__(256) void gat_agg_kernel(
    const int* __restrict__ src,
    const float* __restrict__ hres,
    float* __restrict__ out,
    int slot, int do_act, int do_mean)
{
    const int gw = (blockIdx.x * blockDim.x + threadIdx.x) >> 5;
    if (gw >= NN) return;
    const int lane = threadIdx.x & 31;
    const int n = gw;
    const int e0 = g_rowptr[n];
    const int e1 = g_rowptr[n + 1];
    const int head = lane >> 3;
    const float ern = g_er[n * 4 + head];
    float m = fdec(g_elmax_u[slot][head]) + ern;
    m = (m > 0.f) ? m : 0.2f * m;

    float ssum = 0.f;
    float4 acc = make_float4(0.f, 0.f, 0.f, 0.f);
    const float4* feat4 = reinterpret_cast<const float4*>(g_feat);

    for (int basee = e0; basee < e1; basee += 32) {
        int idx = basee + lane;
        int sw = (idx < e1) ? __ldg(&src[idx]) : 0;
        int lim = e1 - basee;
        if (lim > 32) lim = 32;
        for (int c = 0; c < lim; c += 8) {
            #pragma unroll
            for (int j = 0; j < 8; j++) {
                int jj = c + j;
                int s = __shfl_sync(0xffffffffu, sw, jj);
                float e = __ldg(&g_el[s * 4 + head]) + ern;
                e = (e > 0.f) ? e : 0.2f * e;          // leaky_relu(0.2)
                float wgt = (jj < lim) ? __expf(e - m) : 0.f;
                ssum += wgt;
                float4 f = __ldg(&feat4[s * 32 + lane]);
                acc.x = fmaf(wgt, f.x, acc.x);
                acc.y = fmaf(wgt, f.y, acc.y);
                acc.z = fmaf(wgt, f.z, acc.z);
                acc.w = fmaf(wgt, f.w, acc.w);
            }
        }
    }

    float inv = (e1 > e0) ? (1.f / ssum) : 0.f;
    float4 o = make_float4(acc.x * inv, acc.y * inv, acc.z * inv, acc.w * inv);

    if (hres) {
        float4 r = __ldg(&reinterpret_cast<const float4*>(hres)[n * 32 + lane]);
        o.x += r.x; o.y += r.y; o.z += r.z; o.w += r.w;
    }
    if (do_act) {  // ELU(alpha=1)
        o.x = (o.x > 0.f) ? o.x : expm1f(o.x);
        o.y = (o.y > 0.f) ? o.y : expm1f(o.y);
        o.z = (o.z > 0.f) ? o.z : expm1f(o.z);
        o.w = (o.w > 0.f) ? o.w : expm1f(o.w);
    }

    if (do_mean) {
        o.x += __shfl_xor_sync(0xffffffffu, o.x, 8);
        o.y += __shfl_xor_sync(0xffffffffu, o.y, 8);
        o.z += __shfl_xor_sync(0xffffffffu, o.z, 8);
        o.w += __shfl_xor_sync(0xffffffffu, o.w, 8);
        o.x += __shfl_xor_sync(0xffffffffu, o.x, 16);
        o.y += __shfl_xor_sync(0xffffffffu, o.y, 16);
        o.z += __shfl_xor_sync(0xffffffffu, o.z, 16);
        o.w += __shfl_xor_sync(0xffffffffu, o.w, 16);
        if (lane < 8) {
            reinterpret_cast<float4*>(out)[n * 8 + lane] =
                make_float4(o.x * 0.25f, o.y * 0.25f, o.z * 0.25f, o.w * 0.25f);
        }
    } else {
        reinterpret_cast<float4*>(out)[n * 32 + lane] = o;
    }
}

// ---------------- launcher --------------------------------------------------
extern "C" void kernel_launch(void* const* d_in, const int* in_sizes, int n_in,
                              void* d_out, int out_size)
{
    const float* x   = (const float*)d_in[0];
    const int*   src = (const int*)d_in[1];
    const int*   dst = (const int*)d_in[2];
    const float* W0  = (const float*)d_in[3];
    const float* al0 = (const float*)d_in[4];
    const float* ar0 = (const float*)d_in[5];
    const float* W1  = (const float*)d_in[6];
    const float* al1 = (const float*)d_in[7];
    const float* ar1 = (const float*)d_in[8];
    const float* W2  = (const float*)d_in[9];
    const float* al2 = (const float*)d_in[10];
    const float* ar2 = (const float*)d_in[11];
    float* out = (float*)d_out;

    float *h1 = nullptr, *h2 = nullptr;
    cudaGetSymbolAddress((void**)&h1, g_h1);
    cudaGetSymbolAddress((void**)&h2, g_h2);

    const int mma_smem = 2 * MT * ALD * (int)sizeof(float);  // 139264 B
    static int smem_set = 0;
    if (!smem_set) {
        cudaFuncSetAttribute(mma_kernel,
                             cudaFuncAttributeMaxDynamicSharedMemorySize, mma_smem);
        smem_set = 1;
    }

    const int mma_grid    = (NN + MT - 1) / MT;     // 391
    const int scores_grid = (NN * 32 + 255) / 256;  // 6250
    const int agg_grid    = (NN * 32) / 256;        // 6250

    rowptr_kernel<<<(NN + 1 + 255) / 256, 256>>>(dst);

    // layer 0
    wprep_kernel<<<1, 256>>>(W0, al0, ar0);
    mma_kernel<<<mma_grid, 256, mma_smem>>>(x, W0);
    scores_kernel<<<scores_grid, 256>>>(x, 0);
    gat_agg_kernel<<<agg_grid, 256>>>(src, nullptr, h1, 0, 1, 0);

    // layer 1 (residual h1)
    wprep_kernel<<<1, 256>>>(W1, al1, ar1);
    mma_kernel<<<mma_grid, 256, mma_smem>>>(h1, W1);
    scores_kernel<<<scores_grid, 256>>>(h1, 1);
    gat_agg_kernel<<<agg_grid, 256>>>(src, h1, h2, 1, 1, 0);

    // layer 2 (residual h2, mean over heads)
    wprep_kernel<<<1, 256>>>(W2, al2, ar2);
    mma_kernel<<<mma_grid, 256, mma_smem>>>(h2, W2);
    scores_kernel<<<scores_grid, 256>>>(h2, 2);
    gat_agg_kernel<<<agg_grid, 256>>>(src, h2, out, 2, 0, 1);
}

// round 10
// speedup vs baseline: 1.3484x; 1.3484x over previous
#include <cuda_runtime.h>
#include <cuda_fp16.h>
#include <mma.h>
#include <math.h>
#include <stdint.h>

using namespace nvcuda;

#define NN 50000
#define NE 800000
#define F  128
#define MT 128        // rows per MMA block
#define HLD 136       // half leading dim for A/B smem (mult of 8)
#define CLD 132       // float leading dim for C staging
#define SPAD 65       // scores transposed-tile pad (odd -> conflict-free LDS)

// ---------------- scratch (device globals; no allocation allowed) ----------
__device__ __align__(16) __half g_feath[NN * F];
__device__ __align__(16) float g_h1[NN * F];
__device__ __align__(16) float g_h2[NN * F];
__device__ __align__(16) float g_el[NN * 4];
__device__ __align__(16) float g_er[NN * 4];
__device__ __align__(16) float g_wl[4 * F];   // W @ al[h]
__device__ __align__(16) float g_wr[4 * F];   // W @ ar[h]
__device__ int g_rowptr[NN + 1];
__device__ unsigned g_elmax_u[3][4];

// ---------------- monotone float<->uint encode for atomicMax ---------------
__device__ __forceinline__ unsigned fenc(float f) {
    unsigned u = __float_as_uint(f);
    return (u & 0x80000000u) ? ~u : (u | 0x80000000u);
}
__device__ __forceinline__ float fdec(unsigned u) {
    return (u & 0x80000000u) ? __uint_as_float(u ^ 0x80000000u)
                             : __uint_as_float(~u);
}

// ---------------- row_ptr (sorted dst, lower_bound) + elmax reset ----------
__global__ void rowptr_kernel(const int* __restrict__ dst) {
    int n = blockIdx.x * blockDim.x + threadIdx.x;
    if (blockIdx.x == 0 && threadIdx.x < 12)
        ((unsigned*)g_elmax_u)[threadIdx.x] = fenc(-3.0e38f);
    if (n > NN) return;
    int lo = 0, hi = NE;
    while (lo < hi) {
        int mid = (lo + hi) >> 1;
        if (dst[mid] < n) lo = mid + 1; else hi = mid;
    }
    g_rowptr[n] = lo;
}

// ---------------- fp16 WMMA GEMM: feat = h @ W  (+ wl/wr on block 0) -------
// 128x128 tile, 256 threads / 8 warps (2 col x 4 row warp grid, warp=32x64).
// A,B staged fp16 (69.6KB -> 2 CTA/SM). C restaged fp32 in same smem, then
// coalesced fp16 feat writeout.
extern __shared__ __align__(16) char s_raw[];

__global__ __launch_bounds__(256) void mma_kernel(
    const float* __restrict__ hin, const float* __restrict__ W,
    const float* __restrict__ al, const float* __restrict__ ar)
{
    __half* As = reinterpret_cast<__half*>(s_raw);               // [128][HLD]
    __half* Bs = reinterpret_cast<__half*>(s_raw) + MT * HLD;    // [128][HLD]
    float*  Cs = reinterpret_cast<float*>(s_raw);                // [128][CLD]
    const int tid  = threadIdx.x;
    const int base = blockIdx.x * MT;

    // block 0: compute wl[h]=W@al[h], wr[h]=W@ar[h] (exact fp32)
    if (blockIdx.x == 0) {
        #pragma unroll
        for (int j = 0; j < 4; j++) {
            int o = tid + 256 * j;                 // 1024 outputs
            int k = o & 127, hh = o >> 7, h = hh & 3;
            const float* vec = (hh < 4) ? al : ar;
            float s = 0.f;
            #pragma unroll
            for (int d = 0; d < 32; d++)
                s = fmaf(__ldg(&W[k * F + h * 32 + d]), __ldg(&vec[h * 32 + d]), s);
            if (hh < 4) g_wl[h * F + k] = s; else g_wr[h * F + k] = s;
        }
    }

    // ---- fill A (h tile, fp16) and B (W, fp16), coalesced ----
    #pragma unroll
    for (int i = 0; i < 16; i++) {
        int idx = tid + 256 * i;          // 4096 float4 source slots
        int row = idx >> 5, c4 = idx & 31;
        int n = base + row;
        float4 v = (n < NN)
            ? __ldg(reinterpret_cast<const float4*>(&hin[n * F + 4 * c4]))
            : make_float4(0.f, 0.f, 0.f, 0.f);
        __half2 a01 = __floats2half2_rn(v.x, v.y);
        __half2 a23 = __floats2half2_rn(v.z, v.w);
        uint2 pa;
        pa.x = *reinterpret_cast<unsigned*>(&a01);
        pa.y = *reinterpret_cast<unsigned*>(&a23);
        *reinterpret_cast<uint2*>(&As[row * HLD + 4 * c4]) = pa;

        float4 wv = __ldg(reinterpret_cast<const float4*>(&W[idx * 4]));
        __half2 b01 = __floats2half2_rn(wv.x, wv.y);
        __half2 b23 = __floats2half2_rn(wv.z, wv.w);
        uint2 pb;
        pb.x = *reinterpret_cast<unsigned*>(&b01);
        pb.y = *reinterpret_cast<unsigned*>(&b23);
        *reinterpret_cast<uint2*>(&Bs[row * HLD + 4 * c4]) = pb;  // row=k here
    }
    __syncthreads();

    const int w  = tid >> 5;
    const int wr = w & 3;       // rows 32*wr .. +31
    const int wc = w >> 2;      // cols 64*wc .. +63

    wmma::fragment<wmma::accumulator, 16, 16, 16, float> c[2][4];
    #pragma unroll
    for (int i = 0; i < 2; i++)
        #pragma unroll
        for (int j = 0; j < 4; j++) wmma::fill_fragment(c[i][j], 0.f);

    #pragma unroll
    for (int k = 0; k < 8; k++) {
        wmma::fragment<wmma::matrix_a, 16, 16, 16, __half, wmma::row_major> a[2];
        wmma::fragment<wmma::matrix_b, 16, 16, 16, __half, wmma::row_major> b[4];
        #pragma unroll
        for (int i = 0; i < 2; i++)
            wmma::load_matrix_sync(a[i], &As[(32 * wr + 16 * i) * HLD + 16 * k], HLD);
        #pragma unroll
        for (int j = 0; j < 4; j++)
            wmma::load_matrix_sync(b[j], &Bs[16 * k * HLD + 64 * wc + 16 * j], HLD);
        #pragma unroll
        for (int i = 0; i < 2; i++)
            #pragma unroll
            for (int j = 0; j < 4; j++)
                wmma::mma_sync(c[i][j], a[i], b[j], c[i][j]);
    }
    __syncthreads();   // done reading A/B before reuse as C staging

    #pragma unroll
    for (int i = 0; i < 2; i++)
        #pragma unroll
        for (int j = 0; j < 4; j++)
            wmma::store_matrix_sync(
                &Cs[(32 * wr + 16 * i) * CLD + 64 * wc + 16 * j],
                c[i][j], CLD, wmma::mem_row_major);
    __syncthreads();

    // ---- coalesced fp16 feat writeout ----
    #pragma unroll
    for (int i = 0; i < 16; i++) {
        int idx = tid + 256 * i;
        int row = idx >> 5, c4 = idx & 31;
        int n = base + row;
        if (n < NN) {
            float4 v = *reinterpret_cast<const float4*>(&Cs[row * CLD + 4 * c4]);
            __half2 p01 = __floats2half2_rn(v.x, v.y);
            __half2 p23 = __floats2half2_rn(v.z, v.w);
            uint2 pk;
            pk.x = *reinterpret_cast<unsigned*>(&p01);
            pk.y = *reinterpret_cast<unsigned*>(&p23);
            *reinterpret_cast<uint2*>(&g_feath[n * F + 4 * c4]) = pk;
        }
    }
}

// ---------------- exact fp32 scores v2: el/er = h @ wl/wr + elmax ----------
// 64 rows per block, 256 threads. h tile staged TRANSPOSED (pad 65 ->
// conflict-free scalar LDS). Thread = (row, head): full 128-dot, no shuffles.
__global__ __launch_bounds__(256) void scores_kernel(
    const float* __restrict__ hin, int slot)
{
    __shared__ float hsT[F * SPAD];     // 33.3 KB
    __shared__ unsigned shm[4];
    const int tid = threadIdx.x;
    const int base = blockIdx.x * 64;
    if (tid < 4) shm[tid] = fenc(-3.0e38f);

    // fill transposed: coalesced LDG (warp = 32 col-groups of one row)
    {
        const int k4 = tid & 31, r0 = tid >> 5;
        #pragma unroll
        for (int j = 0; j < 8; j++) {
            int r = r0 + 8 * j;
            int n = base + r;
            float4 v = (n < NN)
                ? __ldg(reinterpret_cast<const float4*>(&hin[n * F + 4 * k4]))
                : make_float4(0.f, 0.f, 0.f, 0.f);
            hsT[(4 * k4 + 0) * SPAD + r] = v.x;
            hsT[(4 * k4 + 1) * SPAD + r] = v.y;
            hsT[(4 * k4 + 2) * SPAD + r] = v.z;
            hsT[(4 * k4 + 3) * SPAD + r] = v.w;
        }
    }
    __syncthreads();

    const int r  = tid & 63;
    const int hd = tid >> 6;
    const int n  = base + r;
    float el = 0.f, er = 0.f;
    const float4* wl4 = reinterpret_cast<const float4*>(g_wl);
    const float4* wr4 = reinterpret_cast<const float4*>(g_wr);
    #pragma unroll 8
    for (int k4 = 0; k4 < 32; k4++) {
        float4 wlv = __ldg(&wl4[hd * 32 + k4]);
        float4 wrv = __ldg(&wr4[hd * 32 + k4]);
        float h0 = hsT[(4 * k4 + 0) * SPAD + r];
        float h1 = hsT[(4 * k4 + 1) * SPAD + r];
        float h2 = hsT[(4 * k4 + 2) * SPAD + r];
        float h3 = hsT[(4 * k4 + 3) * SPAD + r];
        el = fmaf(h0, wlv.x, fmaf(h1, wlv.y, fmaf(h2, wlv.z, fmaf(h3, wlv.w, el))));
        er = fmaf(h0, wrv.x, fmaf(h1, wrv.y, fmaf(h2, wrv.z, fmaf(h3, wrv.w, er))));
    }
    if (n < NN) {
        g_el[n * 4 + hd] = el;
        g_er[n * 4 + hd] = er;
        atomicMax(&shm[hd], fenc(el));
    }
    __syncthreads();
    if (tid < 4) atomicMax(&g_elmax_u[slot][tid], shm[tid]);
}

// ---------------- single-pass edge softmax + aggregation -------------------
__global__ __launch_bounds__(256) void gat_agg_kernel(
    const int* __restrict__ src,
    const float* __restrict__ hres,
    float* __restrict__ out,
    int slot, int do_act, int do_mean)
{
    const int gw = (blockIdx.x * blockDim.x + threadIdx.x) >> 5;
    if (gw >= NN) return;
    const int lane = threadIdx.x & 31;
    const int n = gw;
    const int e0 = g_rowptr[n];
    const int e1 = g_rowptr[n + 1];
    const int head = lane >> 3;
    const float ern = g_er[n * 4 + head];
    float m = fdec(g_elmax_u[slot][head]) + ern;
    m = (m > 0.f) ? m : 0.2f * m;

    float ssum = 0.f;
    float4 acc = make_float4(0.f, 0.f, 0.f, 0.f);
    const uint2* feat8 = reinterpret_cast<const uint2*>(g_feath);

    for (int basee = e0; basee < e1; basee += 32) {
        int idx = basee + lane;
        int sw = (idx < e1) ? __ldg(&src[idx]) : 0;
        int lim = e1 - basee;
        if (lim > 32) lim = 32;
        for (int c = 0; c < lim; c += 8) {
            #pragma unroll
            for (int j = 0; j < 8; j++) {
                int jj = c + j;
                int s = __shfl_sync(0xffffffffu, sw, jj);
                float e = __ldg(&g_el[s * 4 + head]) + ern;
                e = (e > 0.f) ? e : 0.2f * e;          // leaky_relu(0.2)
                float wgt = (jj < lim) ? __expf(e - m) : 0.f;
                ssum += wgt;
                uint2 pk = __ldg(&feat8[s * 32 + lane]);
                float2 f01 = __half22float2(*reinterpret_cast<__half2*>(&pk.x));
                float2 f23 = __half22float2(*reinterpret_cast<__half2*>(&pk.y));
                acc.x = fmaf(wgt, f01.x, acc.x);
                acc.y = fmaf(wgt, f01.y, acc.y);
                acc.z = fmaf(wgt, f23.x, acc.z);
                acc.w = fmaf(wgt, f23.y, acc.w);
            }
        }
    }

    float inv = (e1 > e0) ? (1.f / ssum) : 0.f;
    float4 o = make_float4(acc.x * inv, acc.y * inv, acc.z * inv, acc.w * inv);

    if (hres) {
        float4 rr = __ldg(&reinterpret_cast<const float4*>(hres)[n * 32 + lane]);
        o.x += rr.x; o.y += rr.y; o.z += rr.z; o.w += rr.w;
    }
    if (do_act) {  // ELU(alpha=1)
        o.x = (o.x > 0.f) ? o.x : expm1f(o.x);
        o.y = (o.y > 0.f) ? o.y : expm1f(o.y);
        o.z = (o.z > 0.f) ? o.z : expm1f(o.z);
        o.w = (o.w > 0.f) ? o.w : expm1f(o.w);
    }

    if (do_mean) {
        o.x += __shfl_xor_sync(0xffffffffu, o.x, 8);
        o.y += __shfl_xor_sync(0xffffffffu, o.y, 8);
        o.z += __shfl_xor_sync(0xffffffffu, o.z, 8);
        o.w += __shfl_xor_sync(0xffffffffu, o.w, 8);
        o.x += __shfl_xor_sync(0xffffffffu, o.x, 16);
        o.y += __shfl_xor_sync(0xffffffffu, o.y, 16);
        o.z += __shfl_xor_sync(0xffffffffu, o.z, 16);
        o.w += __shfl_xor_sync(0xffffffffu, o.w, 16);
        if (lane < 8) {
            reinterpret_cast<float4*>(out)[n * 8 + lane] =
                make_float4(o.x * 0.25f, o.y * 0.25f, o.z * 0.25f, o.w * 0.25f);
        }
    } else {
        reinterpret_cast<float4*>(out)[n * 32 + lane] = o;
    }
}

// ---------------- launcher --------------------------------------------------
extern "C" void kernel_launch(void* const* d_in, const int* in_sizes, int n_in,
                              void* d_out, int out_size)
{
    const float* x   = (const float*)d_in[0];
    const int*   src = (const int*)d_in[1];
    const int*   dst = (const int*)d_in[2];
    const float* W0  = (const float*)d_in[3];
    const float* al0 = (const float*)d_in[4];
    const float* ar0 = (const float*)d_in[5];
    const float* W1  = (const float*)d_in[6];
    const float* al1 = (const float*)d_in[7];
    const float* ar1 = (const float*)d_in[8];
    const float* W2  = (const float*)d_in[9];
    const float* al2 = (const float*)d_in[10];
    const float* ar2 = (const float*)d_in[11];
    float* out = (float*)d_out;

    float *h1 = nullptr, *h2 = nullptr;
    cudaGetSymbolAddress((void**)&h1, g_h1);
    cudaGetSymbolAddress((void**)&h2, g_h2);

    const int mma_smem = 2 * MT * HLD * (int)sizeof(__half);  // 69632 B
    static int smem_set = 0;
    if (!smem_set) {
        cudaFuncSetAttribute(mma_kernel,
                             cudaFuncAttributeMaxDynamicSharedMemorySize, mma_smem);
        smem_set = 1;
    }

    const int mma_grid    = (NN + MT - 1) / MT;   // 391
    const int scores_grid = (NN + 63) / 64;       // 782
    const int agg_grid    = (NN * 32) / 256;      // 6250

    rowptr_kernel<<<(NN + 1 + 255) / 256, 256>>>(dst);

    // layer 0
    mma_kernel<<<mma_grid, 256, mma_smem>>>(x, W0, al0, ar0);
    scores_kernel<<<scores_grid, 256>>>(x, 0);
    gat_agg_kernel<<<agg_grid, 256>>>(src, nullptr, h1, 0, 1, 0);

    // layer 1 (residual h1)
    mma_kernel<<<mma_grid, 256, mma_smem>>>(h1, W1, al1, ar1);
    scores_kernel<<<scores_grid, 256>>>(h1, 1);
    gat_agg_kernel<<<agg_grid, 256>>>(src, h1, h2, 1, 1, 0);

    // layer 2 (residual h2, mean over heads)
    mma_kernel<<<mma_grid, 256, mma_smem>>>(h2, W2, al2, ar2);
    scores_kernel<<<scores_grid, 256>>>(h2, 2);
    gat_agg_kernel<<<agg_grid, 256>>>(src, h2, out, 2, 0, 1);
}